// round 1
// baseline (speedup 1.0000x reference)
#include <cuda_runtime.h>

// Problem constants
#define B_TOTAL 4096
#define T 28
#define IN_F 28
#define H 128
#define L 10
#define C 10
#define BT 32                 // batch rows per block
#define NBLK (B_TOTAL / BT)   // 128 blocks

// Ping-pong activation buffers [B][T][H] (L2-resident: 2 x 58.7MB vs 126MB L2)
__device__ float g_buf0[B_TOTAL * T * H];
__device__ float g_buf1[B_TOTAL * T * H];

// Dynamic shared layout (floats):
//   sWihT [128][128]  (k-major, transposed input weights; layer0 uses [28][128])
//   sWhhT [128][128]  (k-major, transposed recurrent weights)
//   sIn   [32][128]   staged input tile for current timestep
//   sH    [32][128]   hidden state
//   sBias [128]
#define SMEM_FLOATS (H * H * 2 + BT * H * 2 + H)
#define SMEM_BYTES (SMEM_FLOATS * 4)

__device__ __forceinline__ float accurate_tanh(float v) {
    // tanh(x) = 1 - 2/(exp(2x)+1); __expf rel err ~1e-6, saturates correctly at +-inf
    float e = __expf(2.0f * v);
    return 1.0f - 2.0f / (e + 1.0f);
}

// acc[4][4] += A[b0..b0+3][:K] * W^T  where sW is stored [k][h] (k-major)
// tx selects h columns tx*4..tx*4+3 ; ty selects batch rows ty*4..ty*4+3
__device__ __forceinline__ void gemm_phase(float acc[4][4],
                                           const float* __restrict__ sA,
                                           const float* __restrict__ sW,
                                           int nk4, int ty, int tx) {
    const float4* A4 = (const float4*)sA;
    const float4* W4 = (const float4*)sW;
#pragma unroll 2
    for (int k4 = 0; k4 < nk4; ++k4) {
        float4 a[4];
#pragma unroll
        for (int i = 0; i < 4; ++i)
            a[i] = A4[(ty * 4 + i) * (H / 4) + k4];  // warp-broadcast (same addr across tx)
#pragma unroll
        for (int kk = 0; kk < 4; ++kk) {
            float4 w = W4[(k4 * 4 + kk) * (H / 4) + tx];  // conflict-free LDS.128
#pragma unroll
            for (int i = 0; i < 4; ++i) {
                float av = ((const float*)&a[i])[kk];
                acc[i][0] = fmaf(av, w.x, acc[i][0]);
                acc[i][1] = fmaf(av, w.y, acc[i][1]);
                acc[i][2] = fmaf(av, w.z, acc[i][2]);
                acc[i][3] = fmaf(av, w.w, acc[i][3]);
            }
        }
    }
}

__global__ void __launch_bounds__(256, 1)
rnn_kernel(const float* __restrict__ x,
           const float* __restrict__ Wih0,
           const float* __restrict__ Wih,
           const float* __restrict__ Whh,
           const float* __restrict__ bih,
           const float* __restrict__ bhh,
           const float* __restrict__ fcW,
           const float* __restrict__ fcb,
           float* __restrict__ out) {
    extern __shared__ float smem[];
    float* sWihT = smem;                 // H*H
    float* sWhhT = sWihT + H * H;        // H*H
    float* sIn   = sWhhT + H * H;        // BT*H
    float* sH    = sIn + BT * H;         // BT*H
    float* sBias = sH + BT * H;          // H

    const int tx = threadIdx.x;              // 0..31 -> h cols h0 = tx*4
    const int ty = threadIdx.y;              // 0..7  -> rows  b0 = ty*4
    const int tid = ty * 32 + tx;
    const int bBase = blockIdx.x * BT;

    for (int layer = 0; layer < L; ++layer) {
        // sync: previous layer's sH writeback must finish before we zero sH / reload weights
        __syncthreads();

        const int Kin = (layer == 0) ? IN_F : H;
        const float* Wl = (layer == 0) ? Wih0 : (Wih + (layer - 1) * H * H);
        for (int idx = tid; idx < H * Kin; idx += 256) {
            int h = idx / Kin, k = idx - h * Kin;
            sWihT[k * H + h] = Wl[idx];
        }
        const float* Wr = Whh + layer * H * H;
        for (int idx = tid; idx < H * H; idx += 256) {
            int h = idx >> 7, k = idx & 127;
            sWhhT[k * H + h] = Wr[idx];
        }
        if (tid < H) sBias[tid] = bih[layer * H + tid] + bhh[layer * H + tid];
        for (int idx = tid; idx < BT * H; idx += 256) sH[idx] = 0.0f;
        // __syncthreads happens at top of t loop (S1)

        const float* bufIn = ((layer & 1) ? g_buf0 : g_buf1);  // prev layer's output
        float* bufOut = ((layer & 1) ? g_buf1 : g_buf0);

        for (int t = 0; t < T; ++t) {
            // ---- stage input tile for this timestep ----
            if (layer == 0) {
                for (int idx = tid; idx < BT * IN_F; idx += 256) {
                    int b = idx / IN_F, f = idx - b * IN_F;
                    sIn[b * H + f] = x[(bBase + b) * (T * IN_F) + t * IN_F + f];
                }
            } else {
                for (int idx = tid; idx < BT * H; idx += 256) {
                    int b = idx >> 7, h = idx & 127;
                    sIn[b * H + h] = bufIn[((bBase + b) * T + t) * H + h];
                }
            }
            __syncthreads();  // S1: staging done, previous sH writes visible

            // ---- acc = bias ; acc += in_t @ Wih^T ; acc += h @ Whh^T ----
            float acc[4][4];
#pragma unroll
            for (int j = 0; j < 4; ++j) {
                float bv = sBias[tx * 4 + j];
#pragma unroll
                for (int i = 0; i < 4; ++i) acc[i][j] = bv;
            }
            gemm_phase(acc, sIn, sWihT, Kin / 4, ty, tx);
            gemm_phase(acc, sH, sWhhT, H / 4, ty, tx);

            __syncthreads();  // S2: all reads of sH done before overwrite

            // ---- tanh + writeback ----
#pragma unroll
            for (int i = 0; i < 4; ++i) {
                int b = ty * 4 + i;
                float4 v4;
                v4.x = accurate_tanh(acc[i][0]);
                v4.y = accurate_tanh(acc[i][1]);
                v4.z = accurate_tanh(acc[i][2]);
                v4.w = accurate_tanh(acc[i][3]);
                ((float4*)&sH[b * H])[tx] = v4;
                if (layer < L - 1) {
                    ((float4*)&bufOut[((bBase + b) * T + t) * H])[tx] = v4;
                }
            }
            // next iteration's S1 orders these writes vs next compute
        }
    }

    __syncthreads();  // final sH writeback visible

    // ---- FC on last hidden state: out[b][c] = h . fcW[c] + fcb[c] ----
    for (int idx = tid; idx < BT * C; idx += 256) {
        int b = idx / C, c = idx - b * C;
        float acc = fcb[c];
        const float* w = fcW + c * H;
        const float* hrow = sH + b * H;
#pragma unroll 8
        for (int k = 0; k < H; ++k) acc = fmaf(hrow[k], w[k], acc);
        out[(bBase + b) * C + c] = acc;
    }
}

extern "C" void kernel_launch(void* const* d_in, const int* in_sizes, int n_in,
                              void* d_out, int out_size) {
    const float* x    = (const float*)d_in[0];
    const float* Wih0 = (const float*)d_in[1];
    const float* Wih  = (const float*)d_in[2];
    const float* Whh  = (const float*)d_in[3];
    const float* bih  = (const float*)d_in[4];
    const float* bhh  = (const float*)d_in[5];
    const float* fcW  = (const float*)d_in[6];
    const float* fcb  = (const float*)d_in[7];
    float* out = (float*)d_out;

    cudaFuncSetAttribute(rnn_kernel, cudaFuncAttributeMaxDynamicSharedMemorySize,
                         SMEM_BYTES);

    dim3 block(32, 8);
    rnn_kernel<<<NBLK, block, SMEM_BYTES>>>(x, Wih0, Wih, Whh, bih, bhh, fcW, fcb, out);
}

// round 2
// speedup vs baseline: 1.3208x; 1.3208x over previous
#include <cuda_runtime.h>

// Problem constants
#define B_TOTAL 4096
#define T 28
#define IN_F 28
#define H 128
#define L 10
#define C 10
#define BT 32                 // batch rows per block
#define NBLK (B_TOTAL / BT)   // 128 blocks

typedef unsigned long long ull;

// Ping-pong activation buffers [B][T][H] (L2-resident: 2 x 58.7MB vs 126MB L2)
__device__ float g_buf0[B_TOTAL * T * H];
__device__ float g_buf1[B_TOTAL * T * H];

// Shared layout (floats):
//  sWihT [128][128] k-major transposed input weights (layer0: rows 0..31, padded)
//  sWhhT [128][128] k-major transposed recurrent weights
//  sIn0  [32][128]  input tile (double buffer A)
//  sIn1  [32][128]  input tile (double buffer B)
//  sH    [32][128]  hidden state
//  sRed  [32][128]  partial sums from recurrent group
//  sBias [128]
#define SMEM_FLOATS (H * H * 2 + BT * H * 4 + H)
#define SMEM_BYTES (SMEM_FLOATS * 4)

// ---- packed f32x2 helpers (sm_100+ PTX; ptxas won't auto-fuse these) ----
__device__ __forceinline__ ull fma2(ull a, ull b, ull c) {
    ull d;
    asm("fma.rn.f32x2 %0, %1, %2, %3;" : "=l"(d) : "l"(a), "l"(b), "l"(c));
    return d;
}
__device__ __forceinline__ ull add2(ull a, ull b) {
    ull d;
    asm("add.rn.f32x2 %0, %1, %2;" : "=l"(d) : "l"(a), "l"(b));
    return d;
}
__device__ __forceinline__ ull pack2(float x, float y) {
    ull d;
    asm("mov.b64 %0, {%1, %2};" : "=l"(d) : "f"(x), "f"(y));
    return d;
}
__device__ __forceinline__ float2 unpack2(ull v) {
    float2 r;
    asm("mov.b64 {%0, %1}, %2;" : "=f"(r.x), "=f"(r.y) : "l"(v));
    return r;
}

__device__ __forceinline__ float accurate_tanh(float v) {
    // tanh(x) = 1 - 2/(exp(2x)+1); __expf rel err ~1e-6, saturates at +-inf
    float e = __expf(2.0f * v);
    return 1.0f - 2.0f / (e + 1.0f);
}

// acc[4 rows][4 j-pairs] += A[b0..b0+3][0:4*nk4] @ W^T, W stored k-major [k][h].
// j0 = 8-aligned output column base. W pairs load as aligned 64-bit lanes (no packs).
__device__ __forceinline__ void gemm2(ull acc[4][4],
                                      const float* __restrict__ sA,
                                      const float* __restrict__ sW,
                                      int nk4, int b0, int j0) {
    const float4* A4 = (const float4*)sA;
#pragma unroll 2
    for (int k4 = 0; k4 < nk4; ++k4) {
        float4 a[4];
#pragma unroll
        for (int i = 0; i < 4; ++i)
            a[i] = A4[(b0 + i) * (H / 4) + k4];   // 2-way dedup across warp
#pragma unroll
        for (int kk = 0; kk < 4; ++kk) {
            const int k = k4 * 4 + kk;
            // two LDS.128 -> four aligned f32x2 weight pairs, zero pack cost
            double2 wA = *(const double2*)&sW[k * H + j0];
            double2 wB = *(const double2*)&sW[k * H + j0 + 4];
            ull w0 = __double_as_longlong(wA.x);
            ull w1 = __double_as_longlong(wA.y);
            ull w2 = __double_as_longlong(wB.x);
            ull w3 = __double_as_longlong(wB.y);
#pragma unroll
            for (int i = 0; i < 4; ++i) {
                float av = (kk == 0) ? a[i].x : (kk == 1) ? a[i].y
                         : (kk == 2) ? a[i].z : a[i].w;
                ull a2 = pack2(av, av);           // 1 ALU op per 4 FFMA2
                acc[i][0] = fma2(a2, w0, acc[i][0]);
                acc[i][1] = fma2(a2, w1, acc[i][1]);
                acc[i][2] = fma2(a2, w2, acc[i][2]);
                acc[i][3] = fma2(a2, w3, acc[i][3]);
            }
        }
    }
}

// Stage one timestep's input tile into dst (layer0: 32 cols, zero-padded past 28)
__device__ __forceinline__ void stage_in(float* __restrict__ dst,
                                         const float* __restrict__ x,
                                         const float* __restrict__ bufIn,
                                         int layer, int t, int bBase,
                                         int li, int nthreads) {
    if (layer == 0) {
        for (int idx = li; idx < BT * 32; idx += nthreads) {
            int b = idx >> 5, f = idx & 31;
            dst[b * H + f] = (f < IN_F)
                ? x[(bBase + b) * (T * IN_F) + t * IN_F + f] : 0.0f;
        }
    } else {
        for (int idx = li; idx < BT * (H / 4); idx += nthreads) {
            int b = idx >> 5, c = idx & 31;
            ((float4*)dst)[idx] =
                *(const float4*)&bufIn[((bBase + b) * T + t) * H + c * 4];
        }
    }
}

__global__ void __launch_bounds__(256, 1)
rnn_kernel(const float* __restrict__ x,
           const float* __restrict__ Wih0,
           const float* __restrict__ Wih,
           const float* __restrict__ Whh,
           const float* __restrict__ bih,
           const float* __restrict__ bhh,
           const float* __restrict__ fcW,
           const float* __restrict__ fcb,
           float* __restrict__ out) {
    extern __shared__ float smem[];
    float* sWihT = smem;                  // H*H
    float* sWhhT = sWihT + H * H;         // H*H
    float* sIn0  = sWhhT + H * H;         // BT*H
    float* sIn1  = sIn0 + BT * H;         // BT*H
    float* sH    = sIn1 + BT * H;         // BT*H
    float* sRed  = sH + BT * H;           // BT*H
    float* sBias = sRed + BT * H;         // H

    const int tid = threadIdx.x;
    const int kg = tid >> 7;              // 0: input-proj group, 1: recurrent group
    const int g  = tid & 127;
    const int jg = g & 15;                // 16 j-groups
    const int bg = g >> 4;                // 8 b-groups
    const int b0 = bg * 4;
    const int j0 = jg * 8;
    const int bBase = blockIdx.x * BT;

    for (int layer = 0; layer < L; ++layer) {
        __syncthreads();   // previous layer fully done with smem / global writes

        const int nk4_in = (layer == 0) ? 8 : 32;
        const int Kin = (layer == 0) ? IN_F : H;
        const float* Wl = (layer == 0) ? Wih0 : (Wih + (layer - 1) * H * H);
        for (int idx = tid; idx < H * Kin; idx += 256) {
            int h = idx / Kin, k = idx - h * Kin;
            sWihT[k * H + h] = Wl[idx];
        }
        if (layer == 0) {   // zero pad rows k=28..31
            for (int idx = tid; idx < 4 * H; idx += 256) {
                int k = 28 + (idx >> 7), h = idx & 127;
                sWihT[k * H + h] = 0.0f;
            }
        }
        const float* Wr = Whh + layer * H * H;
        for (int idx = tid; idx < H * H; idx += 256) {
            int h = idx >> 7, k = idx & 127;
            sWhhT[k * H + h] = Wr[idx];
        }
        if (tid < H) sBias[tid] = bih[layer * H + tid] + bhh[layer * H + tid];
        for (int idx = tid; idx < BT * H; idx += 256) sH[idx] = 0.0f;

        const float* bufIn = (layer & 1) ? g_buf0 : g_buf1;
        float* bufOut = (layer & 1) ? g_buf1 : g_buf0;

        stage_in(sIn0, x, bufIn, layer, 0, bBase, tid, 256);
        __syncthreads();

        for (int t = 0; t < T; ++t) {
            float* sCur = (t & 1) ? sIn1 : sIn0;
            float* sNxt = (t & 1) ? sIn0 : sIn1;

            ull acc[4][4];
            if (kg == 0) {
                // input projection, bias-initialized
#pragma unroll
                for (int jp = 0; jp < 4; ++jp) {
                    ull bv = *(const ull*)&sBias[j0 + 2 * jp];
#pragma unroll
                    for (int i = 0; i < 4; ++i) acc[i][jp] = bv;
                }
                gemm2(acc, sCur, sWihT, nk4_in, b0, j0);
            } else {
                // recurrent matmul into partials
#pragma unroll
                for (int jp = 0; jp < 4; ++jp)
#pragma unroll
                    for (int i = 0; i < 4; ++i) acc[i][jp] = 0ull;
                gemm2(acc, sH, sWhhT, 32, b0, j0);
#pragma unroll
                for (int i = 0; i < 4; ++i)
#pragma unroll
                    for (int jp = 0; jp < 4; ++jp)
                        *(ull*)&sRed[(b0 + i) * H + j0 + 2 * jp] = acc[i][jp];
            }
            __syncthreads();   // S1: partials visible; prev-step sH reads done

            if (kg == 0) {
                // combine + tanh + write hidden state (and next layer's input)
#pragma unroll
                for (int i = 0; i < 4; ++i) {
                    const int b = b0 + i;
                    float o[8];
#pragma unroll
                    for (int jp = 0; jp < 4; ++jp) {
                        ull r = *(const ull*)&sRed[b * H + j0 + 2 * jp];
                        float2 v = unpack2(add2(acc[i][jp], r));
                        o[2 * jp]     = accurate_tanh(v.x);
                        o[2 * jp + 1] = accurate_tanh(v.y);
                    }
                    float4 v0 = make_float4(o[0], o[1], o[2], o[3]);
                    float4 v1 = make_float4(o[4], o[5], o[6], o[7]);
                    *(float4*)&sH[b * H + j0]     = v0;
                    *(float4*)&sH[b * H + j0 + 4] = v1;
                    if (layer < L - 1) {
                        float* orow = &bufOut[((bBase + b) * T + t) * H + j0];
                        *(float4*)orow       = v0;
                        *(float4*)(orow + 4) = v1;
                    }
                }
            } else {
                // overlap: prefetch next timestep's input tile
                if (t + 1 < T)
                    stage_in(sNxt, x, bufIn, layer, t + 1, bBase, g, 128);
            }
            __syncthreads();   // S2: sH / sIn[next] ready for next step
        }
    }

    // ---- FC on last hidden state: out[b][c] = h . fcW[c] + fcb[c] ----
    for (int idx = tid; idx < BT * C; idx += 256) {
        int b = idx / C, c = idx - b * C;
        float acc = fcb[c];
        const float* w = fcW + c * H;
        const float* hrow = sH + b * H;
#pragma unroll 8
        for (int k = 0; k < H; ++k) acc = fmaf(hrow[k], w[k], acc);
        out[(bBase + b) * C + c] = acc;
    }
}

extern "C" void kernel_launch(void* const* d_in, const int* in_sizes, int n_in,
                              void* d_out, int out_size) {
    const float* x    = (const float*)d_in[0];
    const float* Wih0 = (const float*)d_in[1];
    const float* Wih  = (const float*)d_in[2];
    const float* Whh  = (const float*)d_in[3];
    const float* bih  = (const float*)d_in[4];
    const float* bhh  = (const float*)d_in[5];
    const float* fcW  = (const float*)d_in[6];
    const float* fcb  = (const float*)d_in[7];
    float* out = (float*)d_out;

    cudaFuncSetAttribute(rnn_kernel, cudaFuncAttributeMaxDynamicSharedMemorySize,
                         SMEM_BYTES);

    dim3 block(256);
    rnn_kernel<<<NBLK, block, SMEM_BYTES>>>(x, Wih0, Wih, Whh, bih, bhh, fcW, fcb, out);
}

// round 3
// speedup vs baseline: 1.3213x; 1.0004x over previous
#include <cuda_runtime.h>

// Problem constants
#define B_TOTAL 4096
#define T 28
#define IN_F 28
#define H 128
#define L 10
#define C 10
#define BT 32                 // batch rows per block
#define NBLK (B_TOTAL / BT)   // 128 blocks

typedef unsigned long long ull;

// Ping-pong activation buffers [B][T][H] (L2-resident: 2 x 58.7MB vs 126MB L2)
__device__ float g_buf0[B_TOTAL * T * H];
__device__ float g_buf1[B_TOTAL * T * H];

// Shared layout (floats):
//  sWihT [128][128] k-major transposed input weights (layer0: rows 0..31, padded)
//  sWhhT [128][128] k-major transposed recurrent weights
//  sIn0  [32][128]  input tile (double buffer A)
//  sIn1  [32][128]  input tile (double buffer B)
//  sH    [32][128]  hidden state
//  sRed  [32][128]  partial sums from recurrent group
//  sBias [128]
#define SMEM_FLOATS (H * H * 2 + BT * H * 4 + H)
#define SMEM_BYTES (SMEM_FLOATS * 4)

// ---- packed f32x2 helpers (sm_100+ PTX; ptxas won't auto-fuse these) ----
__device__ __forceinline__ ull fma2(ull a, ull b, ull c) {
    ull d;
    asm("fma.rn.f32x2 %0, %1, %2, %3;" : "=l"(d) : "l"(a), "l"(b), "l"(c));
    return d;
}
__device__ __forceinline__ ull add2(ull a, ull b) {
    ull d;
    asm("add.rn.f32x2 %0, %1, %2;" : "=l"(d) : "l"(a), "l"(b));
    return d;
}
__device__ __forceinline__ ull pack2(float x, float y) {
    ull d;
    asm("mov.b64 %0, {%1, %2};" : "=l"(d) : "f"(x), "f"(y));
    return d;
}
__device__ __forceinline__ float2 unpack2(ull v) {
    float2 r;
    asm("mov.b64 {%0, %1}, %2;" : "=f"(r.x), "=f"(r.y) : "l"(v));
    return r;
}

__device__ __forceinline__ float accurate_tanh(float v) {
    // tanh(x) = 1 - 2/(exp(2x)+1); __expf rel err ~1e-6, saturates at +-inf
    float e = __expf(2.0f * v);
    return 1.0f - 2.0f / (e + 1.0f);
}

// acc[4 rows][4 j-pairs] += A[b0..b0+3][0:4*nk4] @ W^T, W stored k-major [k][h].
// j0 = 8-aligned output column base. W pairs load as aligned 64-bit lanes (no packs).
__device__ __forceinline__ void gemm2(ull acc[4][4],
                                      const float* __restrict__ sA,
                                      const float* __restrict__ sW,
                                      int nk4, int b0, int j0) {
    const float4* A4 = (const float4*)sA;
#pragma unroll 2
    for (int k4 = 0; k4 < nk4; ++k4) {
        float4 a[4];
#pragma unroll
        for (int i = 0; i < 4; ++i)
            a[i] = A4[(b0 + i) * (H / 4) + k4];   // 2-way dedup across warp
#pragma unroll
        for (int kk = 0; kk < 4; ++kk) {
            const int k = k4 * 4 + kk;
            // two LDS.128 -> four aligned f32x2 weight pairs, zero pack cost
            double2 wA = *(const double2*)&sW[k * H + j0];
            double2 wB = *(const double2*)&sW[k * H + j0 + 4];
            ull w0 = __double_as_longlong(wA.x);
            ull w1 = __double_as_longlong(wA.y);
            ull w2 = __double_as_longlong(wB.x);
            ull w3 = __double_as_longlong(wB.y);
#pragma unroll
            for (int i = 0; i < 4; ++i) {
                float av = (kk == 0) ? a[i].x : (kk == 1) ? a[i].y
                         : (kk == 2) ? a[i].z : a[i].w;
                ull a2 = pack2(av, av);           // 1 ALU op per 4 FFMA2
                acc[i][0] = fma2(a2, w0, acc[i][0]);
                acc[i][1] = fma2(a2, w1, acc[i][1]);
                acc[i][2] = fma2(a2, w2, acc[i][2]);
                acc[i][3] = fma2(a2, w3, acc[i][3]);
            }
        }
    }
}

// Stage one timestep's input tile into dst (layer0: 32 cols, zero-padded past 28)
__device__ __forceinline__ void stage_in(float* __restrict__ dst,
                                         const float* __restrict__ x,
                                         const float* __restrict__ bufIn,
                                         int layer, int t, int bBase,
                                         int li, int nthreads) {
    if (layer == 0) {
        for (int idx = li; idx < BT * 32; idx += nthreads) {
            int b = idx >> 5, f = idx & 31;
            dst[b * H + f] = (f < IN_F)
                ? x[(bBase + b) * (T * IN_F) + t * IN_F + f] : 0.0f;
        }
    } else {
        for (int idx = li; idx < BT * (H / 4); idx += nthreads) {
            int b = idx >> 5, c = idx & 31;
            ((float4*)dst)[idx] =
                *(const float4*)&bufIn[((bBase + b) * T + t) * H + c * 4];
        }
    }
}

__global__ void __launch_bounds__(256, 1)
rnn_kernel(const float* __restrict__ x,
           const float* __restrict__ Wih0,
           const float* __restrict__ Wih,
           const float* __restrict__ Whh,
           const float* __restrict__ bih,
           const float* __restrict__ bhh,
           const float* __restrict__ fcW,
           const float* __restrict__ fcb,
           float* __restrict__ out) {
    extern __shared__ float smem[];
    float* sWihT = smem;                  // H*H
    float* sWhhT = sWihT + H * H;         // H*H
    float* sIn0  = sWhhT + H * H;         // BT*H
    float* sIn1  = sIn0 + BT * H;         // BT*H
    float* sH    = sIn1 + BT * H;         // BT*H
    float* sRed  = sH + BT * H;           // BT*H
    float* sBias = sRed + BT * H;         // H

    const int tid = threadIdx.x;
    const int kg = tid >> 7;              // 0: input-proj group, 1: recurrent group
    const int g  = tid & 127;
    const int jg = g & 15;                // 16 j-groups
    const int bg = g >> 4;                // 8 b-groups
    const int b0 = bg * 4;
    const int j0 = jg * 8;
    const int bBase = blockIdx.x * BT;

    for (int layer = 0; layer < L; ++layer) {
        __syncthreads();   // previous layer fully done with smem / global writes

        const int nk4_in = (layer == 0) ? 8 : 32;
        const int Kin = (layer == 0) ? IN_F : H;
        const float* Wl = (layer == 0) ? Wih0 : (Wih + (layer - 1) * H * H);
        for (int idx = tid; idx < H * Kin; idx += 256) {
            int h = idx / Kin, k = idx - h * Kin;
            sWihT[k * H + h] = Wl[idx];
        }
        if (layer == 0) {   // zero pad rows k=28..31
            for (int idx = tid; idx < 4 * H; idx += 256) {
                int k = 28 + (idx >> 7), h = idx & 127;
                sWihT[k * H + h] = 0.0f;
            }
        }
        const float* Wr = Whh + layer * H * H;
        for (int idx = tid; idx < H * H; idx += 256) {
            int h = idx >> 7, k = idx & 127;
            sWhhT[k * H + h] = Wr[idx];
        }
        if (tid < H) sBias[tid] = bih[layer * H + tid] + bhh[layer * H + tid];
        for (int idx = tid; idx < BT * H; idx += 256) sH[idx] = 0.0f;

        const float* bufIn = (layer & 1) ? g_buf0 : g_buf1;
        float* bufOut = (layer & 1) ? g_buf1 : g_buf0;

        stage_in(sIn0, x, bufIn, layer, 0, bBase, tid, 256);
        __syncthreads();

        for (int t = 0; t < T; ++t) {
            float* sCur = (t & 1) ? sIn1 : sIn0;
            float* sNxt = (t & 1) ? sIn0 : sIn1;

            ull acc[4][4];
            if (kg == 0) {
                // input projection, bias-initialized
#pragma unroll
                for (int jp = 0; jp < 4; ++jp) {
                    ull bv = *(const ull*)&sBias[j0 + 2 * jp];
#pragma unroll
                    for (int i = 0; i < 4; ++i) acc[i][jp] = bv;
                }
                gemm2(acc, sCur, sWihT, nk4_in, b0, j0);
            } else {
                // recurrent matmul into partials
#pragma unroll
                for (int jp = 0; jp < 4; ++jp)
#pragma unroll
                    for (int i = 0; i < 4; ++i) acc[i][jp] = 0ull;
                gemm2(acc, sH, sWhhT, 32, b0, j0);
#pragma unroll
                for (int i = 0; i < 4; ++i)
#pragma unroll
                    for (int jp = 0; jp < 4; ++jp)
                        *(ull*)&sRed[(b0 + i) * H + j0 + 2 * jp] = acc[i][jp];
            }
            __syncthreads();   // S1: partials visible; prev-step sH reads done

            if (kg == 0) {
                // combine + tanh + write hidden state (and next layer's input)
#pragma unroll
                for (int i = 0; i < 4; ++i) {
                    const int b = b0 + i;
                    float o[8];
#pragma unroll
                    for (int jp = 0; jp < 4; ++jp) {
                        ull r = *(const ull*)&sRed[b * H + j0 + 2 * jp];
                        float2 v = unpack2(add2(acc[i][jp], r));
                        o[2 * jp]     = accurate_tanh(v.x);
                        o[2 * jp + 1] = accurate_tanh(v.y);
                    }
                    float4 v0 = make_float4(o[0], o[1], o[2], o[3]);
                    float4 v1 = make_float4(o[4], o[5], o[6], o[7]);
                    *(float4*)&sH[b * H + j0]     = v0;
                    *(float4*)&sH[b * H + j0 + 4] = v1;
                    if (layer < L - 1) {
                        float* orow = &bufOut[((bBase + b) * T + t) * H + j0];
                        *(float4*)orow       = v0;
                        *(float4*)(orow + 4) = v1;
                    }
                }
            } else {
                // overlap: prefetch next timestep's input tile
                if (t + 1 < T)
                    stage_in(sNxt, x, bufIn, layer, t + 1, bBase, g, 128);
            }
            __syncthreads();   // S2: sH / sIn[next] ready for next step
        }
    }

    // ---- FC on last hidden state: out[b][c] = h . fcW[c] + fcb[c] ----
    for (int idx = tid; idx < BT * C; idx += 256) {
        int b = idx / C, c = idx - b * C;
        float acc = fcb[c];
        const float* w = fcW + c * H;
        const float* hrow = sH + b * H;
#pragma unroll 8
        for (int k = 0; k < H; ++k) acc = fmaf(hrow[k], w[k], acc);
        out[(bBase + b) * C + c] = acc;
    }
}

extern "C" void kernel_launch(void* const* d_in, const int* in_sizes, int n_in,
                              void* d_out, int out_size) {
    const float* x    = (const float*)d_in[0];
    const float* Wih0 = (const float*)d_in[1];
    const float* Wih  = (const float*)d_in[2];
    const float* Whh  = (const float*)d_in[3];
    const float* bih  = (const float*)d_in[4];
    const float* bhh  = (const float*)d_in[5];
    const float* fcW  = (const float*)d_in[6];
    const float* fcb  = (const float*)d_in[7];
    float* out = (float*)d_out;

    cudaFuncSetAttribute(rnn_kernel, cudaFuncAttributeMaxDynamicSharedMemorySize,
                         SMEM_BYTES);

    dim3 block(256);
    rnn_kernel<<<NBLK, block, SMEM_BYTES>>>(x, Wih0, Wih, Whh, bih, bhh, fcW, fcb, out);
}

// round 5
// speedup vs baseline: 3.5997x; 2.7244x over previous
#include <cuda_runtime.h>
#include <cuda_bf16.h>
#include <cstdint>

#define B_TOTAL 4096
#define T 28
#define IN_F 28
#define H 128
#define L 10
#define C 10
#define BT 32
#define NBLK 128   // 4096/32

typedef uint32_t u32;

// Inter-layer activation planes: verbatim swizzled-SMEM tile images, ping-pong.
// One tile = 32 rows x 256B = 8KB = 512 uint4.
__device__ uint4 g_hi[2][NBLK * T * 512];
__device__ uint4 g_lo[2][NBLK * T * 512];

// ---- SMEM byte offsets ----
#define O_WIH_HI 0
#define O_WIH_LO 32768
#define O_WHH_HI 65536
#define O_WHH_LO 98304
#define O_X0_HI 131072
#define O_X0_LO 139264
#define O_X1_HI 147456
#define O_X1_LO 155648
#define O_H_HI  163840
#define O_H_LO  172032
#define O_HF    180224
#define SMEM_BYTES 196608

static __device__ __forceinline__ u32 smem_u32(const void* p) {
    u32 a;
    asm("{ .reg .u64 t; cvta.to.shared.u64 t, %1; cvt.u32.u64 %0, t; }" : "=r"(a) : "l"(p));
    return a;
}
// XOR-swizzled [row][128 bf16] tile: 16B chunk c of row r lives at chunk (c ^ (r&7)).
static __device__ __forceinline__ u32 swz(int row, int col) {
    return (u32)(row * 256 + ((((col >> 3) ^ (row & 7))) << 4) + (col & 7) * 2);
}
static __device__ __forceinline__ void ldsm4(u32 r[4], u32 a) {
    asm volatile("ldmatrix.sync.aligned.m8n8.x4.shared.b16 {%0,%1,%2,%3}, [%4];"
                 : "=r"(r[0]), "=r"(r[1]), "=r"(r[2]), "=r"(r[3]) : "r"(a));
}
static __device__ __forceinline__ void ldsm2(u32 r[2], u32 a) {
    asm volatile("ldmatrix.sync.aligned.m8n8.x2.shared.b16 {%0,%1}, [%2];"
                 : "=r"(r[0]), "=r"(r[1]) : "r"(a));
}
static __device__ __forceinline__ void mma16816(float c[4], const u32 a[4], const u32 b[2]) {
    asm volatile(
        "mma.sync.aligned.m16n8k16.row.col.f32.bf16.bf16.f32 "
        "{%0,%1,%2,%3}, {%4,%5,%6,%7}, {%8,%9}, {%0,%1,%2,%3};"
        : "+f"(c[0]), "+f"(c[1]), "+f"(c[2]), "+f"(c[3])
        : "r"(a[0]), "r"(a[1]), "r"(a[2]), "r"(a[3]), "r"(b[0]), "r"(b[1]));
}
static __device__ __forceinline__ void bf16_split(float v, __nv_bfloat16& hh, __nv_bfloat16& ll) {
    hh = __float2bfloat16(v);
    ll = __float2bfloat16(v - __bfloat162float(hh));
}

__global__ void __launch_bounds__(256, 1)
rnn_mma(const float* __restrict__ x, const float* __restrict__ Wih0,
        const float* __restrict__ Wih, const float* __restrict__ Whh,
        const float* __restrict__ bih, const float* __restrict__ bhh,
        const float* __restrict__ fcW, const float* __restrict__ fcb,
        float* __restrict__ out) {
    extern __shared__ __align__(256) char smem[];
    const u32 sbase = smem_u32(smem);
    const int tid = threadIdx.x;
    const int wid = tid >> 5, lane = tid & 31;
    const int g = lane >> 2, tg = lane & 3;
    const int hc0 = wid * 16;                 // this warp's 16 h-columns
    const int l15 = lane & 15;
    const int arow = lane & 15;               // A-frag row within m-tile
    const int acol = ((lane >> 4) & 1) * 8;   // A-frag col-half within k-chunk
    const int bBase = blockIdx.x * BT;

    // zero X buffers once (layer-0 pad cols 28..127 stay zero)
    {
        uint4 z = make_uint4(0, 0, 0, 0);
        uint4* xb = (uint4*)(smem + O_X0_HI);   // X0_HI..X1_LO contiguous: 4*8KB
        for (int i = tid; i < 2048; i += 256) xb[i] = z;
    }

    // bias column indices for this thread
    const int hcol0 = hc0 + tg * 2;
    const int hcol2 = hc0 + 8 + tg * 2;

#pragma unroll 1
    for (int layer = 0; layer < L; ++layer) {
        __syncthreads();   // previous layer fully done

        // ---- stage weights (bf16 hi/lo) into swizzled tiles ----
        if (layer == 0) {
            for (int i = tid; i < H * H; i += 256) {
                int m = i >> 7, k = i & 127;
                float w = (k < IN_F) ? Wih0[m * IN_F + k] : 0.0f;
                __nv_bfloat16 hh, ll; bf16_split(w, hh, ll);
                u32 o = swz(m, k);
                *(__nv_bfloat16*)(smem + O_WIH_HI + o) = hh;
                *(__nv_bfloat16*)(smem + O_WIH_LO + o) = ll;
            }
        } else {
            const float* Wl = Wih + (layer - 1) * H * H;
            for (int i = tid; i < H * H; i += 256) {
                int m = i >> 7, k = i & 127;
                __nv_bfloat16 hh, ll; bf16_split(Wl[i], hh, ll);
                u32 o = swz(m, k);
                *(__nv_bfloat16*)(smem + O_WIH_HI + o) = hh;
                *(__nv_bfloat16*)(smem + O_WIH_LO + o) = ll;
            }
        }
        {
            const float* Wr = Whh + layer * H * H;
            for (int i = tid; i < H * H; i += 256) {
                int m = i >> 7, k = i & 127;
                __nv_bfloat16 hh, ll; bf16_split(Wr[i], hh, ll);
                u32 o = swz(m, k);
                *(__nv_bfloat16*)(smem + O_WHH_HI + o) = hh;
                *(__nv_bfloat16*)(smem + O_WHH_LO + o) = ll;
            }
        }
        // zero hidden state tiles (t=0 recurrent mma then contributes 0)
        {
            uint4 z = make_uint4(0, 0, 0, 0);
            uint4* hb = (uint4*)(smem + O_H_HI);   // H_HI + H_LO contiguous: 1024 uint4
            for (int i = tid; i < 1024; i += 256) hb[i] = z;
        }

        const int rdp = (layer - 1) & 1, wrp = layer & 1;
        float bsum[4];
        bsum[0] = bih[layer * H + hcol0]     + bhh[layer * H + hcol0];
        bsum[1] = bih[layer * H + hcol0 + 1] + bhh[layer * H + hcol0 + 1];
        bsum[2] = bih[layer * H + hcol2]     + bhh[layer * H + hcol2];
        bsum[3] = bih[layer * H + hcol2 + 1] + bhh[layer * H + hcol2 + 1];

        // ---- stage t=0 input ----
        if (layer == 0) {
            for (int i = tid; i < BT * 32; i += 256) {
                int b = i >> 5, k = i & 31;
                if (k < IN_F) {
                    float v = x[((bBase + b) * T + 0) * IN_F + k];
                    __nv_bfloat16 hh, ll; bf16_split(v, hh, ll);
                    u32 o = swz(b, k);
                    *(__nv_bfloat16*)(smem + O_X0_HI + o) = hh;
                    *(__nv_bfloat16*)(smem + O_X0_LO + o) = ll;
                }
            }
        } else {
            const uint4* sh = g_hi[rdp] + (u32)(blockIdx.x * T + 0) * 512;
            const uint4* sl = g_lo[rdp] + (u32)(blockIdx.x * T + 0) * 512;
            uint4* dh = (uint4*)(smem + O_X0_HI);
            uint4* dl = (uint4*)(smem + O_X0_LO);
            for (int i = tid; i < 512; i += 256) { dh[i] = sh[i]; dl[i] = sl[i]; }
        }
        __syncthreads();

        // ---- load weight fragments into registers (held for all 28 steps) ----
        u32 wih_hi[8][2][2], wih_lo[8][2][2], whh_hi[8][2][2], whh_lo[8][2][2];
#pragma unroll
        for (int kc = 0; kc < 8; ++kc)
#pragma unroll
            for (int nt = 0; nt < 2; ++nt) {
                u32 o = swz(hc0 + nt * 8 + (l15 & 7), kc * 16 + ((l15 >> 3) << 3));
                ldsm2(wih_hi[kc][nt], sbase + O_WIH_HI + o);
                ldsm2(wih_lo[kc][nt], sbase + O_WIH_LO + o);
                ldsm2(whh_hi[kc][nt], sbase + O_WHH_HI + o);
                ldsm2(whh_lo[kc][nt], sbase + O_WHH_LO + o);
            }

#pragma unroll 1
        for (int t = 0; t < T; ++t) {
            const u32 xh = sbase + ((t & 1) ? O_X1_HI : O_X0_HI);
            const u32 xl = sbase + ((t & 1) ? O_X1_LO : O_X0_LO);
            const u32 sh_hi = sbase + O_H_HI, sh_lo = sbase + O_H_LO;

            float acc[2][2][4];
#pragma unroll
            for (int mt = 0; mt < 2; ++mt)
#pragma unroll
                for (int nt = 0; nt < 2; ++nt)
#pragma unroll
                    for (int j = 0; j < 4; ++j) acc[mt][nt][j] = 0.0f;

#pragma unroll
            for (int kc = 0; kc < 8; ++kc) {
#pragma unroll
                for (int mt = 0; mt < 2; ++mt) {
                    u32 ao = swz(mt * 16 + arow, kc * 16 + acol);
                    u32 axh[4], axl[4], ahh[4], ahl[4];
                    ldsm4(axh, xh + ao);
                    ldsm4(axl, xl + ao);
                    ldsm4(ahh, sh_hi + ao);
                    ldsm4(ahl, sh_lo + ao);
#pragma unroll
                    for (int nt = 0; nt < 2; ++nt) {
                        mma16816(acc[mt][nt], axh, wih_hi[kc][nt]);
                        mma16816(acc[mt][nt], ahh, whh_hi[kc][nt]);
                        mma16816(acc[mt][nt], axl, wih_hi[kc][nt]);
                        mma16816(acc[mt][nt], ahl, whh_hi[kc][nt]);
                        mma16816(acc[mt][nt], axh, wih_lo[kc][nt]);
                        mma16816(acc[mt][nt], ahh, whh_lo[kc][nt]);
                    }
                }
            }
            __syncthreads();   // all sH / X reads complete

            // ---- epilogue: bias + tanh + write sH (hi/lo) ----
#pragma unroll
            for (int mt = 0; mt < 2; ++mt)
#pragma unroll
                for (int bs = 0; bs < 2; ++bs) {
                    const int b = mt * 16 + bs * 8 + g;
#pragma unroll
                    for (int nt = 0; nt < 2; ++nt) {
                        float v0 = acc[mt][nt][bs * 2 + 0] + bsum[nt * 2 + 0];
                        float v1 = acc[mt][nt][bs * 2 + 1] + bsum[nt * 2 + 1];
                        float e0 = __expf(2.0f * v0);
                        float e1 = __expf(2.0f * v1);
                        v0 = 1.0f - __fdividef(2.0f, e0 + 1.0f);
                        v1 = 1.0f - __fdividef(2.0f, e1 + 1.0f);
                        const int hcol = hc0 + nt * 8 + tg * 2;
                        __nv_bfloat16 h0, l0, h1, l1;
                        bf16_split(v0, h0, l0);
                        bf16_split(v1, h1, l1);
                        u32 o = swz(b, hcol);
                        *(__nv_bfloat162*)(smem + O_H_HI + o) = __nv_bfloat162(h0, h1);
                        *(__nv_bfloat162*)(smem + O_H_LO + o) = __nv_bfloat162(l0, l1);
                        if (layer == L - 1 && t == T - 1) {
                            ((float*)(smem + O_HF))[b * H + hcol] = v0;
                            ((float*)(smem + O_HF))[b * H + hcol + 1] = v1;
                        }
                    }
                }
            __syncthreads();   // sH tile complete

            // ---- coalesced copy-out of sH image + stage next input ----
            if (layer < L - 1) {
                uint4* dh = g_hi[wrp] + (u32)(blockIdx.x * T + t) * 512;
                uint4* dl = g_lo[wrp] + (u32)(blockIdx.x * T + t) * 512;
                const uint4* shp = (const uint4*)(smem + O_H_HI);
                const uint4* slp = (const uint4*)(smem + O_H_LO);
                for (int i = tid; i < 512; i += 256) { dh[i] = shp[i]; dl[i] = slp[i]; }
            }
            if (t + 1 < T) {
                const u32 nh = sbase + ((t & 1) ? O_X0_HI : O_X1_HI);
                if (layer == 0) {
                    for (int i = tid; i < BT * 32; i += 256) {
                        int b = i >> 5, k = i & 31;
                        if (k < IN_F) {
                            float v = x[((bBase + b) * T + t + 1) * IN_F + k];
                            __nv_bfloat16 hh, ll; bf16_split(v, hh, ll);
                            u32 o = swz(b, k);
                            *(__nv_bfloat16*)(smem + (nh - sbase) + o) = hh;
                            *(__nv_bfloat16*)(smem + (nh - sbase) + 8192 + o) = ll;
                        }
                    }
                } else {
                    const uint4* sh2 = g_hi[rdp] + (u32)(blockIdx.x * T + t + 1) * 512;
                    const uint4* sl2 = g_lo[rdp] + (u32)(blockIdx.x * T + t + 1) * 512;
                    uint4* dh2 = (uint4*)(smem + (nh - sbase));
                    uint4* dl2 = (uint4*)(smem + (nh - sbase) + 8192);
                    for (int i = tid; i < 512; i += 256) { dh2[i] = sh2[i]; dl2[i] = sl2[i]; }
                }
            }
            __syncthreads();   // next-step X ready; copy-out ordered before next overwrite
        }
    }

    // ---- FC on last hidden state ----
    const float* hf = (const float*)(smem + O_HF);
    for (int i = tid; i < BT * C; i += 256) {
        int b = i / C, c = i - b * C;
        float acc = fcb[c];
        const float* w = fcW + c * H;
        const float* hr = hf + b * H;
#pragma unroll 8
        for (int k = 0; k < H; ++k) acc = fmaf(hr[k], w[k], acc);
        out[(bBase + b) * C + c] = acc;
    }
}

extern "C" void kernel_launch(void* const* d_in, const int* in_sizes, int n_in,
                              void* d_out, int out_size) {
    const float* x    = (const float*)d_in[0];
    const float* Wih0 = (const float*)d_in[1];
    const float* Wih  = (const float*)d_in[2];
    const float* Whh  = (const float*)d_in[3];
    const float* bih  = (const float*)d_in[4];
    const float* bhh  = (const float*)d_in[5];
    const float* fcW  = (const float*)d_in[6];
    const float* fcb  = (const float*)d_in[7];
    cudaFuncSetAttribute(rnn_mma, cudaFuncAttributeMaxDynamicSharedMemorySize, SMEM_BYTES);
    rnn_mma<<<NBLK, 256, SMEM_BYTES>>>(x, Wih0, Wih, Whh, bih, bhh, fcW, fcb, (float*)d_out);
}